// round 6
// baseline (speedup 1.0000x reference)
#include <cuda_runtime.h>
#include <cuda_bf16.h>

// Problem: B=32, N=50000, K=32, E=6, F=3
//   f[b,n,f] = leaky_relu(x[b,n]*s[f] + g[n,f]),  s[f]=sum_e W[f,e], g[n,f]=W[f,:].emb[n,:]+bias[f]
//   out[n,k] = mask * mean_b exp(-||f[b,n,:]-f[b,nbr[n,k],:]||^2)          (2*theta = 1)
//
// Identities:
//   lrelu(u) = 0.6u + 0.4|u|; positively homogeneous => pre-scale s,g by
//   sqrt(log2 e) so sum(d^2) is log2-scaled and exp(-d) = ex2(-sum d^2).
//   Inner math done 2 batch-elements at a time with packed f32x2 FMA.

#define NMAX 50000
#define BDIM 32
#define KDIM 32
#define C_SCALE 1.2011224087864498f   // sqrt(log2(e))

__device__ float  g_xT[NMAX * BDIM];   // 6.4 MB, transposed x
__device__ float4 g_g4[NMAX];          // 0.8 MB, pre-scaled g

// ---- packed f32x2 helpers (sm_103a; ptxas won't auto-fuse, must be PTX) ----
typedef unsigned long long u64;

__device__ __forceinline__ u64 pk2(float a, float b) {
    u64 r; asm("mov.b64 %0, {%1, %2};" : "=l"(r) : "f"(a), "f"(b)); return r;
}
__device__ __forceinline__ void unpk2(u64 v, float& a, float& b) {
    asm("mov.b64 {%0, %1}, %2;" : "=f"(a), "=f"(b) : "l"(v));
}
#define FMA2(d, a, b, c) asm("fma.rn.f32x2 %0, %1, %2, %3;" : "=l"(d) : "l"(a), "l"(b), "l"(c))
#define MUL2(d, a, b)    asm("mul.rn.f32x2 %0, %1, %2;"     : "=l"(d) : "l"(a), "l"(b))
#define ADD2(d, a, b)    asm("add.rn.f32x2 %0, %1, %2;"     : "=l"(d) : "l"(a), "l"(b))

#define ABS2_MASK  0x7FFFFFFF7FFFFFFFull
#define SIGN2_MASK 0x8000000080000000ull

// ---------------------------------------------------------------------------
// Kernel 1: transpose x (B,N) -> xT (N,B); compute scaled g4[n].
// ---------------------------------------------------------------------------
__global__ __launch_bounds__(256) void prep_kernel(
    const float* __restrict__ x,      // (B, N)
    const float* __restrict__ emb,    // (N, 6)
    const float* __restrict__ fcw,    // (3, 6)
    const float* __restrict__ fcb,    // (3,)
    int N)
{
    __shared__ float xt[32][33];
    const int n0 = blockIdx.x * 32;
    const int tx = threadIdx.x;
    const int ty = threadIdx.y;

    #pragma unroll
    for (int i = 0; i < 4; i++) {
        int b = ty + 8 * i;
        int n = n0 + tx;
        xt[b][tx] = (n < N) ? x[b * N + n] : 0.0f;
    }
    __syncthreads();

    #pragma unroll
    for (int i = 0; i < 4; i++) {
        int r = ty + 8 * i;
        int n = n0 + r;
        if (n < N) g_xT[n * BDIM + tx] = xt[tx][r];
    }

    const int tid = ty * 32 + tx;
    if (tid < 32) {
        int n = n0 + tid;
        if (n < N) {
            float e0 = emb[n * 6 + 0], e1 = emb[n * 6 + 1], e2 = emb[n * 6 + 2];
            float e3 = emb[n * 6 + 3], e4 = emb[n * 6 + 4], e5 = emb[n * 6 + 5];
            float g[3];
            #pragma unroll
            for (int f = 0; f < 3; f++) {
                g[f] = fcb[f]
                     + fcw[f * 6 + 0] * e0 + fcw[f * 6 + 1] * e1
                     + fcw[f * 6 + 2] * e2 + fcw[f * 6 + 3] * e3
                     + fcw[f * 6 + 4] * e4 + fcw[f * 6 + 5] * e5;
            }
            g_g4[n] = make_float4(C_SCALE * g[0], C_SCALE * g[1],
                                  C_SCALE * g[2], 0.0f);
        }
    }
}

// ---------------------------------------------------------------------------
// Kernel 2: one warp per node.
//   XOR-swizzled neighbor-x staging (no pad -> 32KB, 6 CTAs/SM):
//     element (k, b) lives at word  k*32 + (b ^ ((k&7)<<2)).
//     store (lane=b, loop k): banks (lane ^ c) distinct           -> clean
//     read  (lane=k, float4 unit g^(lane&7)): unit%8 distinct/phase-> clean
//   Inner loop: packed f32x2 math, 2 batch elements per step.
// ---------------------------------------------------------------------------
__global__ __launch_bounds__(256, 6) void pair_kernel(
    const int*  __restrict__ nl,      // (N, 32)
    const float* __restrict__ fcw,    // (3, 6)
    float* __restrict__ out,          // (N, 32)
    int N)
{
    __shared__ float4 xs4[8][KDIM * 8];                     // 32 KB
    __shared__ __align__(16) float fs0[8][32], fs1[8][32], fs2[8][32];

    const int wid  = threadIdx.x >> 5;
    const int lane = threadIdx.x & 31;
    const int n    = blockIdx.x * 8 + wid;
    if (n >= N) return;

    // scaled s[f] = C * sum_e W[f,e]
    float s0 = 0.f, s1 = 0.f, s2 = 0.f;
    #pragma unroll
    for (int e = 0; e < 6; e++) {
        s0 += fcw[e];
        s1 += fcw[6 + e];
        s2 += fcw[12 + e];
    }
    s0 *= C_SCALE; s1 *= C_SCALE; s2 *= C_SCALE;

    // --- Phase 1: lane = b : self f (SoA) ---
    {
        float  xv = g_xT[n * BDIM + lane];
        float4 gs = g_g4[n];
        float u0 = fmaf(xv, s0, gs.x);
        float u1 = fmaf(xv, s1, gs.y);
        float u2 = fmaf(xv, s2, gs.z);
        fs0[wid][lane] = fmaf(0.4f, fabsf(u0), 0.6f * u0);
        fs1[wid][lane] = fmaf(0.4f, fabsf(u1), 0.6f * u1);
        fs2[wid][lane] = fmaf(0.4f, fabsf(u2), 0.6f * u2);
    }

    const int   j    = nl[n * KDIM + lane];
    const int   jc   = (j < 0) ? 0 : j;
    const float mask = (j < 0) ? 0.0f : 1.0f;
    const float4 gj  = g_g4[jc];

    // Stage neighbor x rows, swizzled.
    float* xs = (float*)xs4[wid];
    #pragma unroll 4
    for (int k = 0; k < KDIM; k++) {
        int jj = __shfl_sync(0xffffffffu, jc, k);
        xs[k * 32 + (lane ^ ((k & 7) << 2))] = g_xT[jj * BDIM + lane];
    }
    __syncwarp();

    // --- Phase 2: lane = k, packed f32x2 over b ---
    const u64 s02 = pk2(s0, s0), s12 = pk2(s1, s1), s22 = pk2(s2, s2);
    const u64 g02 = pk2(gj.x, gj.x), g12 = pk2(gj.y, gj.y), g22 = pk2(gj.z, gj.z);
    const u64 n06 = pk2(-0.6f, -0.6f), n04 = pk2(-0.4f, -0.4f);

    const float4* xrow = xs4[wid] + lane * 8;
    const int     sw   = lane & 7;
    float acc0 = 0.0f, acc1 = 0.0f;

    #pragma unroll
    for (int g = 0; g < 8; g++) {
        float4 xv4 = xrow[g ^ sw];                     // b = 4g .. 4g+3
        float4 f0v = *(const float4*)&fs0[wid][g * 4];
        float4 f1v = *(const float4*)&fs1[wid][g * 4];
        float4 f2v = *(const float4*)&fs2[wid][g * 4];

        #define PAIR2(XA, XB, F0A, F0B, F1A, F1B, F2A, F2B)                   \
        {                                                                     \
            u64 xv2 = pk2((XA), (XB));                                        \
            u64 u0, u1, u2, d0, d1, d2, a0, a1, a2, m;                        \
            FMA2(u0, xv2, s02, g02);                                          \
            FMA2(u1, xv2, s12, g12);                                          \
            FMA2(u2, xv2, s22, g22);                                          \
            a0 = u0 & ABS2_MASK; a1 = u1 & ABS2_MASK; a2 = u2 & ABS2_MASK;    \
            d0 = pk2((F0A), (F0B)); FMA2(d0, u0, n06, d0); FMA2(d0, a0, n04, d0); \
            d1 = pk2((F1A), (F1B)); FMA2(d1, u1, n06, d1); FMA2(d1, a1, n04, d1); \
            d2 = pk2((F2A), (F2B)); FMA2(d2, u2, n06, d2); FMA2(d2, a2, n04, d2); \
            MUL2(m, d0, d0); FMA2(m, d1, d1, m); FMA2(m, d2, d2, m);          \
            m ^= SIGN2_MASK;                                                  \
            float mlo, mhi, e0, e1;                                           \
            unpk2(m, mlo, mhi);                                               \
            asm("ex2.approx.ftz.f32 %0, %1;" : "=f"(e0) : "f"(mlo));          \
            asm("ex2.approx.ftz.f32 %0, %1;" : "=f"(e1) : "f"(mhi));          \
            acc0 += e0; acc1 += e1;                                           \
        }

        PAIR2(xv4.x, xv4.y, f0v.x, f0v.y, f1v.x, f1v.y, f2v.x, f2v.y)
        PAIR2(xv4.z, xv4.w, f0v.z, f0v.w, f1v.z, f1v.w, f2v.z, f2v.w)
        #undef PAIR2
    }

    out[n * KDIM + lane] = (acc0 + acc1) * (1.0f / 32.0f) * mask;
}

// ---------------------------------------------------------------------------
extern "C" void kernel_launch(void* const* d_in, const int* in_sizes, int n_in,
                              void* d_out, int out_size)
{
    const float* x    = (const float*)d_in[0];   // (B, N)
    const float* emb  = (const float*)d_in[1];   // (N, 6)
    const float* fcw  = (const float*)d_in[2];   // (3, 6)
    const float* fcb  = (const float*)d_in[3];   // (3,)
    const int*   nl   = (const int*)d_in[4];     // (N, 32)
    float*       out  = (float*)d_out;           // (N, 32)

    const int N = in_sizes[1] / 6;               // 50000

    dim3 b1(32, 8);
    prep_kernel<<<(N + 31) / 32, b1>>>(x, emb, fcw, fcb, N);

    pair_kernel<<<(N + 7) / 8, 256>>>(nl, fcw, out, N);
}